// round 1
// baseline (speedup 1.0000x reference)
#include <cuda_runtime.h>
#include <cuda_bf16.h>
#include <cstdint>

// ---------------------------------------------------------------------------
// TokenDiscrepancyLoss: loss = 0.1/D * sum_{n: mask} ( t_sq_n + S_n / Z_n )
//   Z_n = sum_k exp(x_n . W_k + b_k)
//   S_n = sum_k exp(...) * (||c_k||^2 - 2 * t_n . c_k)
// Shapes: N=B*S=4096, H=1024, K=16384 (derived at runtime from in_sizes).
// ---------------------------------------------------------------------------

#define MAXN 4096
#define MAXK 16384
#define NSPLIT 16
#define TM 64
#define TK 128
#define TH 16

__device__ int   g_cnt;
__device__ int   g_rowidx[MAXN];
__device__ float g_csq[MAXK];
__device__ float g_tsq[MAXN];
__device__ float g_Zpart[MAXN * NSPLIT];
__device__ float g_Spart[MAXN * NSPLIT];

// ---------------------------------------------------------------------------
// Kernel 1: detect int64 vs int32 token_type_ids layout, compact active rows.
// Deterministic: fixed thread->token mapping + block scan.
// ---------------------------------------------------------------------------
__global__ void compact_kernel(const int* tt32, int N) {
    __shared__ int ssum[1024];
    __shared__ int s_is64;
    int tid = threadIdx.x;

    // Layout probe: for int64 data, high 32-bit words (odd int32 slots) are 0
    // (values are 0/1). For int32 data, odd slots hold random 0/1 tokens.
    if (tid == 0) s_is64 = 1;
    __syncthreads();
    if (tid < 128) {
        if (tt32[2 * tid + 1] != 0) atomicAnd(&s_is64, 0);
    }
    __syncthreads();
    int is64 = s_is64;

    int per = (N + blockDim.x - 1) / blockDim.x;  // 4 for N=4096
    if (per > 8) per = 8;
    int base = tid * per;

    int flags[8];
    int cnt = 0;
#pragma unroll
    for (int i = 0; i < 8; i++) flags[i] = 0;
    for (int i = 0; i < per; i++) {
        int idx = base + i;
        int f = 0;
        if (idx < N) {
            int v = is64 ? tt32[2 * idx] : tt32[idx];
            f = (v == 1) ? 1 : 0;
        }
        flags[i] = f;
        cnt += f;
    }
    ssum[tid] = cnt;
    __syncthreads();

    // Hillis-Steele inclusive scan over 1024 thread sums
    for (int off = 1; off < 1024; off <<= 1) {
        int v = (tid >= off) ? ssum[tid - off] : 0;
        __syncthreads();
        ssum[tid] += v;
        __syncthreads();
    }
    int pos = ssum[tid] - cnt;  // exclusive prefix
    for (int i = 0; i < per; i++) {
        if (flags[i]) g_rowidx[pos++] = base + i;
    }
    if (tid == blockDim.x - 1) g_cnt = ssum[tid];
}

// ---------------------------------------------------------------------------
// Kernel 2/3: per-row sum of squares (codebook -> g_csq, targets -> g_tsq)
// One warp per row, float4 loads, shuffle reduce.
// ---------------------------------------------------------------------------
__global__ void rowsq_kernel(const float* __restrict__ M, float* __restrict__ out,
                             int R, int H) {
    int warps_per_cta = blockDim.x >> 5;
    int gw   = blockIdx.x * warps_per_cta + (threadIdx.x >> 5);
    int lane = threadIdx.x & 31;
    int nw   = gridDim.x * warps_per_cta;
    int h4   = H >> 2;
    for (int r = gw; r < R; r += nw) {
        const float4* p = (const float4*)(M + (size_t)r * H);
        float s = 0.f;
        for (int i = lane; i < h4; i += 32) {
            float4 v = p[i];
            s += v.x * v.x + v.y * v.y + v.z * v.z + v.w * v.w;
        }
#pragma unroll
        for (int o = 16; o; o >>= 1) s += __shfl_down_sync(0xffffffffu, s, o);
        if (lane == 0) out[r] = s;
    }
}

// ---------------------------------------------------------------------------
// Kernel 4: fused dual GEMM + exp + partial (Z, S) per (row, split).
// Tile: TM=64 rows x TK=128 K-columns, H streamed in TH=16 chunks.
// 256 threads, each owns a 4x8 sub-block of BOTH accumulators.
// ---------------------------------------------------------------------------
__global__ void __launch_bounds__(256, 2)
main_kernel(const float* __restrict__ X, const float* __restrict__ Tg,
            const float* __restrict__ W, const float* __restrict__ Cb,
            const float* __restrict__ bvec, int H, int K) {
    int cnt = g_cnt;
    int rt  = blockIdx.x;
    if (rt * TM >= cnt) return;
    int split = blockIdx.y;
    int kspan = K / NSPLIT;
    int kbeg  = split * kspan;

    __shared__ float Xs[TH][TM];
    __shared__ float Ts[TH][TM];
    __shared__ float Ws[TH][TK];
    __shared__ float Cs[TH][TK];
    __shared__ int   rows[TM];
    __shared__ float red[TM][16];

    int tid = threadIdx.x;
    if (tid < TM) {
        int slot = rt * TM + tid;
        rows[tid] = (slot < cnt) ? g_rowidx[slot] : g_rowidx[0];
    }
    __syncthreads();

    int tcol = tid & 15;   // owns cols tcol*8 .. tcol*8+7
    int trow = tid >> 4;   // owns rows trow*4 .. trow*4+3

    // X/T loader mapping: each thread loads one float4 per tile
    int lr  = tid >> 2;          // 0..63
    int lhq = (tid & 3) << 2;    // 0,4,8,12
    size_t xoff = (size_t)rows[lr] * (size_t)H + lhq;

    float zacc[4] = {0.f, 0.f, 0.f, 0.f};
    float sacc[4] = {0.f, 0.f, 0.f, 0.f};

    for (int kt = kbeg; kt < kbeg + kspan; kt += TK) {
        float accL[4][8];
        float accC[4][8];
#pragma unroll
        for (int i = 0; i < 4; i++)
#pragma unroll
            for (int j = 0; j < 8; j++) { accL[i][j] = 0.f; accC[i][j] = 0.f; }

        for (int h0 = 0; h0 < H; h0 += TH) {
            // load X / T chunk (transposed into [TH][TM])
            {
                float4 xv = *(const float4*)(X  + xoff + h0);
                float4 tv = *(const float4*)(Tg + xoff + h0);
                Xs[lhq + 0][lr] = xv.x; Xs[lhq + 1][lr] = xv.y;
                Xs[lhq + 2][lr] = xv.z; Xs[lhq + 3][lr] = xv.w;
                Ts[lhq + 0][lr] = tv.x; Ts[lhq + 1][lr] = tv.y;
                Ts[lhq + 2][lr] = tv.z; Ts[lhq + 3][lr] = tv.w;
            }
            // load W / codebook chunk (transposed into [TH][TK]) : 2 reps
#pragma unroll
            for (int rep = 0; rep < 2; rep++) {
                int idx = tid + (rep << 8);
                int kk  = idx >> 2;          // 0..127
                int hq  = (idx & 3) << 2;    // 0,4,8,12
                size_t goff = (size_t)(kt + kk) * (size_t)H + h0 + hq;
                float4 wv = *(const float4*)(W  + goff);
                float4 cv = *(const float4*)(Cb + goff);
                Ws[hq + 0][kk] = wv.x; Ws[hq + 1][kk] = wv.y;
                Ws[hq + 2][kk] = wv.z; Ws[hq + 3][kk] = wv.w;
                Cs[hq + 0][kk] = cv.x; Cs[hq + 1][kk] = cv.y;
                Cs[hq + 2][kk] = cv.z; Cs[hq + 3][kk] = cv.w;
            }
            __syncthreads();

#pragma unroll
            for (int h = 0; h < TH; h++) {
                float ax[4], at[4], bw[8], bc[8];
#pragma unroll
                for (int i = 0; i < 4; i++) {
                    ax[i] = Xs[h][trow * 4 + i];
                    at[i] = Ts[h][trow * 4 + i];
                }
#pragma unroll
                for (int j = 0; j < 8; j++) {
                    bw[j] = Ws[h][tcol * 8 + j];
                    bc[j] = Cs[h][tcol * 8 + j];
                }
#pragma unroll
                for (int i = 0; i < 4; i++)
#pragma unroll
                    for (int j = 0; j < 8; j++) {
                        accL[i][j] = fmaf(ax[i], bw[j], accL[i][j]);
                        accC[i][j] = fmaf(at[i], bc[j], accC[i][j]);
                    }
            }
            __syncthreads();
        }

        // epilogue: exp + accumulate Z,S for this K tile
#pragma unroll
        for (int j = 0; j < 8; j++) {
            int k   = kt + tcol * 8 + j;
            float bk = bvec[k];
            float ck = g_csq[k];
#pragma unroll
            for (int i = 0; i < 4; i++) {
                float e = __expf(accL[i][j] + bk);
                zacc[i] += e;
                sacc[i] = fmaf(e, ck - 2.f * accC[i][j], sacc[i]);
            }
        }
    }

    // reduce across the 16 column-threads per row (deterministic order)
#pragma unroll
    for (int i = 0; i < 4; i++) red[trow * 4 + i][tcol] = zacc[i];
    __syncthreads();
    if (tid < TM) {
        float s = 0.f;
#pragma unroll
        for (int c = 0; c < 16; c++) s += red[tid][c];
        g_Zpart[(rt * TM + tid) * NSPLIT + split] = s;
    }
    __syncthreads();
#pragma unroll
    for (int i = 0; i < 4; i++) red[trow * 4 + i][tcol] = sacc[i];
    __syncthreads();
    if (tid < TM) {
        float s = 0.f;
#pragma unroll
        for (int c = 0; c < 16; c++) s += red[tid][c];
        g_Spart[(rt * TM + tid) * NSPLIT + split] = s;
    }
}

// ---------------------------------------------------------------------------
// Kernel 5: finalize. Combine splits per active row, sum, scale. Deterministic.
// ---------------------------------------------------------------------------
__global__ void finalize_kernel(float* __restrict__ out, int D) {
    __shared__ float sred[1024];
    int tid = threadIdx.x;
    int cnt = g_cnt;
    float local = 0.f;
    for (int slot = tid; slot < cnt; slot += blockDim.x) {
        float Z = 0.f, S = 0.f;
#pragma unroll
        for (int s = 0; s < NSPLIT; s++) {
            Z += g_Zpart[slot * NSPLIT + s];
            S += g_Spart[slot * NSPLIT + s];
        }
        int n = g_rowidx[slot];
        local += g_tsq[n] + S / Z;
    }
    sred[tid] = local;
    __syncthreads();
    for (int o = 512; o; o >>= 1) {
        if (tid < o) sred[tid] += sred[tid + o];
        __syncthreads();
    }
    if (tid == 0) out[0] = sred[0] * (0.1f / (float)D);
}

// ---------------------------------------------------------------------------
extern "C" void kernel_launch(void* const* d_in, const int* in_sizes, int n_in,
                              void* d_out, int out_size) {
    const float* X    = (const float*)d_in[0];   // hidden_states  [N, H]
    const int*   tt32 = (const int*)  d_in[1];   // token_type_ids (int32 or int64)
    const float* Tg   = (const float*)d_in[2];   // target_embeddings [N, H]
    const float* W    = (const float*)d_in[3];   // W_proj   [K, H]
    const float* bp   = (const float*)d_in[4];   // b_proj   [K]
    const float* Cb   = (const float*)d_in[5];   // codebook [K, H]
    float* out = (float*)d_out;

    int N = in_sizes[1];
    int H = in_sizes[0] / N;
    int K = in_sizes[4];

    float* csq_p;  cudaGetSymbolAddress((void**)&csq_p, g_csq);
    float* tsq_p;  cudaGetSymbolAddress((void**)&tsq_p, g_tsq);

    compact_kernel<<<1, 1024>>>(tt32, N);
    rowsq_kernel<<<256, 256>>>(Cb, csq_p, K, H);
    rowsq_kernel<<<64, 256>>>(Tg, tsq_p, N, H);

    dim3 grid((N + TM - 1) / TM, NSPLIT);
    main_kernel<<<grid, 256>>>(X, Tg, W, Cb, bp, H, K);

    finalize_kernel<<<1, 1024>>>(out, H);
}

// round 4
// speedup vs baseline: 3.3216x; 3.3216x over previous
#include <cuda_runtime.h>
#include <cstdint>

// ---------------------------------------------------------------------------
// TokenDiscrepancyLoss via legacy mma.sync (tf32) dual GEMM.
// loss = 0.1/H * sum_{n: mask} ( tsq_n + S_n / Z_n )
//   Z_n = sum_k exp(x_n.W_k + b_k),  S_n = sum_k exp(..)*(csq_k - 2 t_n.c_k)
// N=4096, H=1024, K=16384 (runtime-derived; needs H%16==0, K%256==0).
// Active rows compacted (mask == 1), padded to 128.
// ---------------------------------------------------------------------------

#define MAXN   4096
#define MAXK   16384
#define SEGS   64          // K-segments (grid.y)
#define NSEG   256         // cods per CTA segment
#define NPASS  128         // cods per accumulation pass
#define MROWS  128         // rows per CTA
#define KC     16          // fp32 per H-chunk
#define ROWPAD 20          // floats per SMEM row (80 B)
#define STAGES 4

__device__ int   g_cnt;
__device__ int   g_rowidx[MAXN];
__device__ float g_csq[MAXK];
__device__ float g_tsq[MAXN];
__device__ float g_Zpart[MAXN * SEGS];
__device__ float g_Spart[MAXN * SEGS];

// SMEM map (dynamic)
#define SM_ROWS 0                       // 128 ints
#define SM_REDZ 512                     // [4][128] floats
#define SM_REDS 2560                    // [4][128] floats
#define SM_STG  4608                    // stages
#define ARR_B   (MROWS * ROWPAD * 4)    // 10240 B per array
#define STAGE_B (4 * ARR_B)             // 40960 B per stage
#define SMEM_TOTAL (SM_STG + STAGES * STAGE_B)

// ---------------- helpers ----------------
__device__ __forceinline__ uint32_t smem_u32(const void* p) {
    uint32_t a;
    asm("{ .reg .u64 t; cvta.to.shared.u64 t, %1; cvt.u32.u64 %0, t; }" : "=r"(a) : "l"(p));
    return a;
}
__device__ __forceinline__ void cpa16(uint32_t dst, const float* src) {
    asm volatile("cp.async.cg.shared.global [%0], [%1], 16;" :: "r"(dst), "l"(src) : "memory");
}
__device__ __forceinline__ void cpa_commit() {
    asm volatile("cp.async.commit_group;" ::: "memory");
}
template <int N>
__device__ __forceinline__ void cpa_wait() {
    asm volatile("cp.async.wait_group %0;" :: "n"(N) : "memory");
}

#define LDSM4(r0, r1, r2, r3, addr)                                             \
    asm volatile("ldmatrix.sync.aligned.m8n8.x4.shared.b16 {%0,%1,%2,%3}, [%4];" \
                 : "=r"(r0), "=r"(r1), "=r"(r2), "=r"(r3) : "r"(addr))

#define MMA_TF32(c, a, b0, b1)                                                  \
    asm volatile(                                                               \
        "mma.sync.aligned.m16n8k8.row.col.f32.tf32.tf32.f32 "                   \
        "{%0,%1,%2,%3}, {%4,%5,%6,%7}, {%8,%9}, {%0,%1,%2,%3};"                 \
        : "+f"((c)[0]), "+f"((c)[1]), "+f"((c)[2]), "+f"((c)[3])                \
        : "r"((a)[0]), "r"((a)[1]), "r"((a)[2]), "r"((a)[3]), "r"(b0), "r"(b1))

// ---------------------------------------------------------------------------
// Compact active rows (mask==1) into g_rowidx; handles int64/int32 tokens.
// ---------------------------------------------------------------------------
__global__ void compact_kernel(const int* tt32, int N) {
    __shared__ int ssum[1024];
    __shared__ int s_is64;
    int tid = threadIdx.x;
    if (tid == 0) s_is64 = 1;
    __syncthreads();
    if (tid < 128) {
        if (tt32[2 * tid + 1] != 0) atomicAnd(&s_is64, 0);
    }
    __syncthreads();
    int is64 = s_is64;

    int per = (N + blockDim.x - 1) / blockDim.x;
    if (per > 8) per = 8;
    int base = tid * per;
    int flags[8];
    int cnt = 0;
#pragma unroll
    for (int i = 0; i < 8; i++) flags[i] = 0;
    for (int i = 0; i < per; i++) {
        int idx = base + i;
        int f = 0;
        if (idx < N) {
            int v = is64 ? tt32[2 * idx] : tt32[idx];
            f = (v == 1) ? 1 : 0;
        }
        flags[i] = f;
        cnt += f;
    }
    ssum[tid] = cnt;
    __syncthreads();
    for (int off = 1; off < 1024; off <<= 1) {
        int v = (tid >= off) ? ssum[tid - off] : 0;
        __syncthreads();
        ssum[tid] += v;
        __syncthreads();
    }
    int pos = ssum[tid] - cnt;
    for (int i = 0; i < per; i++) {
        if (flags[i]) g_rowidx[pos++] = base + i;
    }
    if (tid == blockDim.x - 1) g_cnt = ssum[tid];
}

__global__ void rowsq_kernel(const float* __restrict__ M, float* __restrict__ out,
                             int R, int H) {
    int wpc = blockDim.x >> 5;
    int gw = blockIdx.x * wpc + (threadIdx.x >> 5);
    int lane = threadIdx.x & 31;
    int nw = gridDim.x * wpc;
    int h4 = H >> 2;
    for (int r = gw; r < R; r += nw) {
        const float4* p = (const float4*)(M + (size_t)r * H);
        float s = 0.f;
        for (int i = lane; i < h4; i += 32) {
            float4 v = p[i];
            s += v.x * v.x + v.y * v.y + v.z * v.z + v.w * v.w;
        }
#pragma unroll
        for (int o = 16; o; o >>= 1) s += __shfl_down_sync(0xffffffffu, s, o);
        if (lane == 0) out[r] = s;
    }
}

// ---------------------------------------------------------------------------
// Main mma.sync kernel.
// ---------------------------------------------------------------------------
__global__ void __launch_bounds__(512, 1)
mma_kernel(const float* __restrict__ X, const float* __restrict__ Tg,
           const float* __restrict__ W, const float* __restrict__ Cb,
           const float* __restrict__ bvec, int H, int K) {
    extern __shared__ char smem[];
    uint32_t sb = smem_u32(smem);
    int* rows = (int*)smem;
    float* redz = (float*)(smem + SM_REDZ);
    float* reds = (float*)(smem + SM_REDS);

    int tid = threadIdx.x;
    int cnt = g_cnt;
    int rt = blockIdx.x;
    if (rt * MROWS >= cnt) return;
    int seg = blockIdx.y;

    if (tid < MROWS) {
        int slot = rt * MROWS + tid;
        rows[tid] = (slot < cnt) ? g_rowidx[slot] : g_rowidx[0];
    }
    __syncthreads();

    const int lane = tid & 31;
    const int wid = tid >> 5;
    const int wm = wid & 3;   // warp row group (32 rows)
    const int wn = wid >> 2;  // warp col group (32 cods)

    // loader role: array a (0=X,1=T,2=W,3=C), row r
    const int la = tid >> 7;
    const int lr = tid & 127;
    const float* srcXT = ((la == 0) ? X : Tg) + (size_t)rows[lr] * H;  // valid for la<2
    const uint32_t dstb = sb + SM_STG + la * ARR_B + lr * (ROWPAD * 4);

    // ldmatrix per-thread offsets
    const int grp = lane >> 3, idx = lane & 7;
    uint32_t aoff[2], boff[2];
#pragma unroll
    for (int m = 0; m < 2; m++) {
        int r = wm * 32 + m * 16 + idx + (grp & 1) * 8;
        aoff[m] = (uint32_t)(r * (ROWPAD * 4) + ((grp >> 1) * 4) * 4);
    }
#pragma unroll
    for (int j = 0; j < 2; j++) {
        int r = wn * 32 + j * 16 + idx + (grp >> 1) * 8;
        boff[j] = (uint32_t)(r * (ROWPAD * 4) + ((grp & 1) * 4) * 4);
    }
    const uint32_t stg0 = sb + SM_STG;

    float zr[4] = {0.f, 0.f, 0.f, 0.f};
    float sr[4] = {0.f, 0.f, 0.f, 0.f};

    const int hcn = H / KC;  // 64

#pragma unroll 1
    for (int np = 0; np < NSEG / NPASS; np++) {
        const int ntb = seg * NSEG + np * NPASS;
        const float* src = (la < 2) ? srcXT
                                    : (((la == 2) ? W : Cb) + (size_t)(ntb + lr) * H);

        float cL[2][4][4], cC[2][4][4];
#pragma unroll
        for (int m = 0; m < 2; m++)
#pragma unroll
            for (int na = 0; na < 4; na++)
#pragma unroll
                for (int q = 0; q < 4; q++) { cL[m][na][q] = 0.f; cC[m][na][q] = 0.f; }

        __syncthreads();  // all warps done reading stages from previous pass
        // pipeline prologue: stages 0..2
#pragma unroll
        for (int p = 0; p < 3; p++) {
#pragma unroll
            for (int c = 0; c < 4; c++)
                cpa16(dstb + p * STAGE_B + c * 16, src + p * KC + c * 4);
            cpa_commit();
        }

#pragma unroll 1
        for (int hc = 0; hc < hcn; hc++) {
            cpa_wait<2>();
            __syncthreads();
            {
                int nf = hc + 3;
                if (nf < hcn) {
#pragma unroll
                    for (int c = 0; c < 4; c++)
                        cpa16(dstb + (nf & 3) * STAGE_B + c * 16, src + nf * KC + c * 4);
                }
                cpa_commit();
            }

            const uint32_t stg = stg0 + (hc & 3) * STAGE_B;
#pragma unroll
            for (int ks = 0; ks < 2; ks++) {
                const uint32_t ko = ks * 32;  // 8 floats
                uint32_t ax[2][4], at[2][4], bw[2][4], bc[2][4];
#pragma unroll
                for (int m = 0; m < 2; m++) {
                    LDSM4(ax[m][0], ax[m][1], ax[m][2], ax[m][3], stg + aoff[m] + ko);
                    LDSM4(at[m][0], at[m][1], at[m][2], at[m][3],
                          stg + ARR_B + aoff[m] + ko);
                }
#pragma unroll
                for (int j = 0; j < 2; j++) {
                    LDSM4(bw[j][0], bw[j][1], bw[j][2], bw[j][3],
                          stg + 2 * ARR_B + boff[j] + ko);
                    LDSM4(bc[j][0], bc[j][1], bc[j][2], bc[j][3],
                          stg + 3 * ARR_B + boff[j] + ko);
                }
#pragma unroll
                for (int m = 0; m < 2; m++)
#pragma unroll
                    for (int j = 0; j < 2; j++) {
                        MMA_TF32(cL[m][2 * j + 0], ax[m], bw[j][0], bw[j][1]);
                        MMA_TF32(cL[m][2 * j + 1], ax[m], bw[j][2], bw[j][3]);
                        MMA_TF32(cC[m][2 * j + 0], at[m], bc[j][0], bc[j][1]);
                        MMA_TF32(cC[m][2 * j + 1], at[m], bc[j][2], bc[j][3]);
                    }
            }
        }

        // epilogue: exp + Z/S accumulation (registers only)
#pragma unroll
        for (int m = 0; m < 2; m++)
#pragma unroll
            for (int na = 0; na < 4; na++) {
                int colb = ntb + wn * 32 + na * 8 + (lane & 3) * 2;
                float2 bb = *(const float2*)(bvec + colb);
                float2 cq = *(const float2*)(&g_csq[colb]);
#pragma unroll
                for (int h = 0; h < 2; h++) {
#pragma unroll
                    for (int q = 0; q < 2; q++) {
                        float e = __expf(cL[m][na][h * 2 + q] + (q ? bb.y : bb.x));
                        float dd = (q ? cq.y : cq.x) - 2.f * cC[m][na][h * 2 + q];
                        zr[m * 2 + h] += e;
                        sr[m * 2 + h] = fmaf(e, dd, sr[m * 2 + h]);
                    }
                }
            }
    }

    // reduce over lane%4 (quad) — all lanes get sum, deterministic
#pragma unroll
    for (int i = 0; i < 4; i++) {
        zr[i] += __shfl_xor_sync(0xffffffffu, zr[i], 1);
        zr[i] += __shfl_xor_sync(0xffffffffu, zr[i], 2);
        sr[i] += __shfl_xor_sync(0xffffffffu, sr[i], 1);
        sr[i] += __shfl_xor_sync(0xffffffffu, sr[i], 2);
    }
    if ((lane & 3) == 0) {
#pragma unroll
        for (int m = 0; m < 2; m++)
#pragma unroll
            for (int h = 0; h < 2; h++) {
                int rloc = wm * 32 + m * 16 + h * 8 + (lane >> 2);
                redz[wn * 128 + rloc] = zr[m * 2 + h];
                reds[wn * 128 + rloc] = sr[m * 2 + h];
            }
    }
    __syncthreads();
    if (tid < MROWS) {
        float Z = 0.f, S = 0.f;
#pragma unroll
        for (int w = 0; w < 4; w++) {
            Z += redz[w * 128 + tid];
            S += reds[w * 128 + tid];
        }
        int slot = rt * MROWS + tid;
        g_Zpart[slot * SEGS + seg] = Z;
        g_Spart[slot * SEGS + seg] = S;
    }
}

// ---------------------------------------------------------------------------
__global__ void finalize_kernel(float* __restrict__ out, int D) {
    __shared__ float sred[1024];
    int tid = threadIdx.x;
    int cnt = g_cnt;
    float local = 0.f;
    for (int slot = tid; slot < cnt; slot += blockDim.x) {
        float Z = 0.f, S = 0.f;
#pragma unroll
        for (int s = 0; s < SEGS; s++) {
            Z += g_Zpart[slot * SEGS + s];
            S += g_Spart[slot * SEGS + s];
        }
        int n = g_rowidx[slot];
        local += g_tsq[n] + S / Z;
    }
    sred[tid] = local;
    __syncthreads();
    for (int o = 512; o; o >>= 1) {
        if (tid < o) sred[tid] += sred[tid + o];
        __syncthreads();
    }
    if (tid == 0) out[0] = sred[0] * (0.1f / (float)D);
}

// ---------------------------------------------------------------------------
extern "C" void kernel_launch(void* const* d_in, const int* in_sizes, int n_in,
                              void* d_out, int out_size) {
    const float* X    = (const float*)d_in[0];
    const int*   tt32 = (const int*)  d_in[1];
    const float* Tg   = (const float*)d_in[2];
    const float* W    = (const float*)d_in[3];
    const float* bp   = (const float*)d_in[4];
    const float* Cb   = (const float*)d_in[5];
    float* out = (float*)d_out;

    int N = in_sizes[1];
    int H = in_sizes[0] / N;
    int K = in_sizes[4];

    float* csq_p; cudaGetSymbolAddress((void**)&csq_p, g_csq);
    float* tsq_p; cudaGetSymbolAddress((void**)&tsq_p, g_tsq);

    cudaFuncSetAttribute(mma_kernel, cudaFuncAttributeMaxDynamicSharedMemorySize,
                         SMEM_TOTAL);

    compact_kernel<<<1, 1024>>>(tt32, N);
    rowsq_kernel<<<256, 256>>>(Cb, csq_p, K, H);
    rowsq_kernel<<<64, 256>>>(Tg, tsq_p, N, H);

    dim3 grid(N / MROWS, K / NSEG);
    mma_kernel<<<grid, 512, SMEM_TOTAL>>>(X, Tg, W, Cb, bp, H, K);

    finalize_kernel<<<1, 1024>>>(out, H);
}

// round 5
// speedup vs baseline: 7.4732x; 2.2499x over previous
#include <cuda_runtime.h>
#include <cuda_bf16.h>
#include <cstdint>

// ---------------------------------------------------------------------------
// TokenDiscrepancyLoss via mma.sync m16n8k16 (bf16) dual GEMM.
// loss = 0.1/H * sum_{n: mask} ( tsq_n + S_n / Z_n )
// Inputs pre-converted fp32->bf16 into __device__ buffers.
// N=4096, H=1024, K=16384 runtime-derived (needs H%32==0, K%256==0).
// ---------------------------------------------------------------------------

#define MAXN   4096
#define MAXH   1024
#define MAXK   16384
#define SEGS   64          // K-segments (grid.y)
#define NSEG   256         // cods per CTA segment
#define NPASS  128         // cods per accumulation pass
#define MROWS  128         // rows per CTA
#define SK     32          // bf16 elems per pipeline stage (64 B/row)
#define ROWB   80          // SMEM bytes per row (64 payload + pad)
#define STAGES 3

__device__ int   g_cnt;
__device__ int   g_rowidx[MAXN];
__device__ float g_csq[MAXK];
__device__ float g_tsq[MAXN];
__device__ float g_Zpart[MAXN * SEGS];
__device__ float g_Spart[MAXN * SEGS];
__device__ __nv_bfloat16 g_Xb[MAXN * MAXH];
__device__ __nv_bfloat16 g_Tb[MAXN * MAXH];
__device__ __nv_bfloat16 g_Wb[MAXK * MAXH];
__device__ __nv_bfloat16 g_Cb[MAXK * MAXH];

// SMEM map (dynamic)
#define SM_REDZ 512
#define SM_REDS 2560
#define SM_STG  4608
#define ARR_B   (MROWS * ROWB)        // 10240 B
#define STAGE_B (4 * ARR_B)           // 40960 B
#define SMEM_TOTAL (SM_STG + STAGES * STAGE_B)

// ---------------- helpers ----------------
__device__ __forceinline__ uint32_t smem_u32(const void* p) {
    uint32_t a;
    asm("{ .reg .u64 t; cvta.to.shared.u64 t, %1; cvt.u32.u64 %0, t; }" : "=r"(a) : "l"(p));
    return a;
}
__device__ __forceinline__ void cpa16(uint32_t dst, const void* src) {
    asm volatile("cp.async.cg.shared.global [%0], [%1], 16;" :: "r"(dst), "l"(src) : "memory");
}
__device__ __forceinline__ void cpa_commit() {
    asm volatile("cp.async.commit_group;" ::: "memory");
}
template <int N>
__device__ __forceinline__ void cpa_wait() {
    asm volatile("cp.async.wait_group %0;" :: "n"(N) : "memory");
}

#define LDSM4(r0, r1, r2, r3, addr)                                             \
    asm volatile("ldmatrix.sync.aligned.m8n8.x4.shared.b16 {%0,%1,%2,%3}, [%4];" \
                 : "=r"(r0), "=r"(r1), "=r"(r2), "=r"(r3) : "r"(addr))

#define MMA_BF16(c, a, b0, b1)                                                  \
    asm volatile(                                                               \
        "mma.sync.aligned.m16n8k16.row.col.f32.bf16.bf16.f32 "                  \
        "{%0,%1,%2,%3}, {%4,%5,%6,%7}, {%8,%9}, {%0,%1,%2,%3};"                 \
        : "+f"((c)[0]), "+f"((c)[1]), "+f"((c)[2]), "+f"((c)[3])                \
        : "r"((a)[0]), "r"((a)[1]), "r"((a)[2]), "r"((a)[3]), "r"(b0), "r"(b1))

// ---------------------------------------------------------------------------
__global__ void compact_kernel(const int* tt32, int N) {
    __shared__ int ssum[1024];
    __shared__ int s_is64;
    int tid = threadIdx.x;
    if (tid == 0) s_is64 = 1;
    __syncthreads();
    if (tid < 128) {
        if (tt32[2 * tid + 1] != 0) atomicAnd(&s_is64, 0);
    }
    __syncthreads();
    int is64 = s_is64;

    int per = (N + blockDim.x - 1) / blockDim.x;
    if (per > 8) per = 8;
    int base = tid * per;
    int flags[8];
    int cnt = 0;
#pragma unroll
    for (int i = 0; i < 8; i++) flags[i] = 0;
    for (int i = 0; i < per; i++) {
        int idx = base + i;
        int f = 0;
        if (idx < N) {
            int v = is64 ? tt32[2 * idx] : tt32[idx];
            f = (v == 1) ? 1 : 0;
        }
        flags[i] = f;
        cnt += f;
    }
    ssum[tid] = cnt;
    __syncthreads();
    for (int off = 1; off < 1024; off <<= 1) {
        int v = (tid >= off) ? ssum[tid - off] : 0;
        __syncthreads();
        ssum[tid] += v;
        __syncthreads();
    }
    int pos = ssum[tid] - cnt;
    for (int i = 0; i < per; i++) {
        if (flags[i]) g_rowidx[pos++] = base + i;
    }
    if (tid == blockDim.x - 1) g_cnt = ssum[tid];
}

__global__ void rowsq_kernel(const float* __restrict__ M, float* __restrict__ out,
                             int R, int H) {
    int wpc = blockDim.x >> 5;
    int gw = blockIdx.x * wpc + (threadIdx.x >> 5);
    int lane = threadIdx.x & 31;
    int nw = gridDim.x * wpc;
    int h4 = H >> 2;
    for (int r = gw; r < R; r += nw) {
        const float4* p = (const float4*)(M + (size_t)r * H);
        float s = 0.f;
        for (int i = lane; i < h4; i += 32) {
            float4 v = p[i];
            s += v.x * v.x + v.y * v.y + v.z * v.z + v.w * v.w;
        }
#pragma unroll
        for (int o = 16; o; o >>= 1) s += __shfl_down_sync(0xffffffffu, s, o);
        if (lane == 0) out[r] = s;
    }
}

__global__ void cvt_bf16_kernel(const float* __restrict__ src,
                                __nv_bfloat16* __restrict__ dst, int n) {
    int stride = gridDim.x * blockDim.x * 4;
    for (int i = (blockIdx.x * blockDim.x + threadIdx.x) * 4; i < n; i += stride) {
        float4 v = *(const float4*)(src + i);
        __nv_bfloat162 a = __float22bfloat162_rn(make_float2(v.x, v.y));
        __nv_bfloat162 b = __float22bfloat162_rn(make_float2(v.z, v.w));
        *(__nv_bfloat162*)(dst + i) = a;
        *(__nv_bfloat162*)(dst + i + 2) = b;
    }
}

// ---------------------------------------------------------------------------
// Main bf16 mma kernel: CTA = 128 rows x NSEG cods (2 passes of 128).
// 512 threads = 16 warps (4 row-groups x 4 col-groups), warp tile 32x32 dual.
// ---------------------------------------------------------------------------
__global__ void __launch_bounds__(512, 1)
mma_kernel(const float* __restrict__ bvec, int H, int K) {
    extern __shared__ char smem[];
    uint32_t sb = smem_u32(smem);
    int* rows = (int*)smem;
    float* redz = (float*)(smem + SM_REDZ);
    float* reds = (float*)(smem + SM_REDS);

    int tid = threadIdx.x;
    int cnt = g_cnt;
    int rt = blockIdx.x;
    if (rt * MROWS >= cnt) return;
    int seg = blockIdx.y;

    if (tid < MROWS) {
        int slot = rt * MROWS + tid;
        rows[tid] = (slot < cnt) ? g_rowidx[slot] : g_rowidx[0];
    }
    __syncthreads();

    const int lane = tid & 31;
    const int wid = tid >> 5;
    const int wm = wid & 3;
    const int wn = wid >> 2;

    // loader role: la = array (0=X,1=T,2=W,3=C); within array: 128 threads,
    // item c in 0..3: row = (t>>2) + 32*c, chunk = t&3 (16B each, 64B/row).
    const int la = tid >> 7;
    const int lt = tid & 127;
    const int lchunk = lt & 3;
    int lrow_g[4];   // global element row offsets
#pragma unroll
    for (int c = 0; c < 4; c++) {
        int r = (lt >> 2) + 32 * c;
        lrow_g[c] = (la == 0 || la == 1) ? rows[r] : r;  // W/C: relative, add ntb later
    }
    const __nv_bfloat16* gbase =
        (la == 0) ? g_Xb : (la == 1) ? g_Tb : (la == 2) ? g_Wb : g_Cb;
    uint32_t ldst[4];
#pragma unroll
    for (int c = 0; c < 4; c++)
        ldst[c] = sb + SM_STG + la * ARR_B + ((lt >> 2) + 32 * c) * ROWB + lchunk * 16;

    // ldmatrix offsets
    const int grp = lane >> 3, idx = lane & 7;
    uint32_t aoff[2], boff[2];
#pragma unroll
    for (int m = 0; m < 2; m++)
        aoff[m] = (uint32_t)((wm * 32 + m * 16 + idx + (grp & 1) * 8) * ROWB +
                             (grp >> 1) * 16);
#pragma unroll
    for (int nb = 0; nb < 2; nb++)
        boff[nb] = (uint32_t)((wn * 32 + nb * 16 + idx + (grp >> 1) * 8) * ROWB +
                              (grp & 1) * 16);
    const uint32_t stg0 = sb + SM_STG;

    float zr[4] = {0.f, 0.f, 0.f, 0.f};
    float sr[4] = {0.f, 0.f, 0.f, 0.f};

    const int hcn = H / SK;  // 32

#pragma unroll 1
    for (int np = 0; np < NSEG / NPASS; np++) {
        const int ntb = seg * NSEG + np * NPASS;

        float cL[2][4][4], cC[2][4][4];
#pragma unroll
        for (int m = 0; m < 2; m++)
#pragma unroll
            for (int nf = 0; nf < 4; nf++)
#pragma unroll
                for (int q = 0; q < 4; q++) { cL[m][nf][q] = 0.f; cC[m][nf][q] = 0.f; }

        __syncthreads();  // stages from previous pass fully consumed

        // per-thread GMEM row bases for this pass
        const __nv_bfloat16* srcs[4];
#pragma unroll
        for (int c = 0; c < 4; c++) {
            int gr = lrow_g[c] + ((la >= 2) ? ntb : 0);
            srcs[c] = gbase + (size_t)gr * H + lchunk * 8;
        }

        // prologue: stages 0,1
#pragma unroll
        for (int p = 0; p < 2; p++) {
#pragma unroll
            for (int c = 0; c < 4; c++)
                cpa16(ldst[c] + p * STAGE_B, srcs[c] + p * SK);
            cpa_commit();
        }

#pragma unroll 1
        for (int hc = 0; hc < hcn; hc++) {
            cpa_wait<1>();
            __syncthreads();
            {
                int nf = hc + 2;
                if (nf < hcn) {
                    uint32_t so = (uint32_t)((nf % STAGES) * STAGE_B);
#pragma unroll
                    for (int c = 0; c < 4; c++)
                        cpa16(ldst[c] + so, srcs[c] + nf * SK);
                }
                cpa_commit();
            }

            const uint32_t stg = stg0 + (hc % STAGES) * STAGE_B;
#pragma unroll
            for (int s = 0; s < 2; s++) {
                const uint32_t ko = s * 32;  // 16 bf16 = 32 B
                uint32_t ax[2][4], at[2][4], bw[2][4], bc[2][4];
#pragma unroll
                for (int m = 0; m < 2; m++) {
                    LDSM4(ax[m][0], ax[m][1], ax[m][2], ax[m][3],
                          stg + aoff[m] + ko);
                    LDSM4(at[m][0], at[m][1], at[m][2], at[m][3],
                          stg + ARR_B + aoff[m] + ko);
                }
#pragma unroll
                for (int nb = 0; nb < 2; nb++) {
                    LDSM4(bw[nb][0], bw[nb][1], bw[nb][2], bw[nb][3],
                          stg + 2 * ARR_B + boff[nb] + ko);
                    LDSM4(bc[nb][0], bc[nb][1], bc[nb][2], bc[nb][3],
                          stg + 3 * ARR_B + boff[nb] + ko);
                }
#pragma unroll
                for (int m = 0; m < 2; m++)
#pragma unroll
                    for (int nb = 0; nb < 2; nb++) {
                        MMA_BF16(cL[m][2 * nb + 0], ax[m], bw[nb][0], bw[nb][1]);
                        MMA_BF16(cL[m][2 * nb + 1], ax[m], bw[nb][2], bw[nb][3]);
                        MMA_BF16(cC[m][2 * nb + 0], at[m], bc[nb][0], bc[nb][1]);
                        MMA_BF16(cC[m][2 * nb + 1], at[m], bc[nb][2], bc[nb][3]);
                    }
            }
        }

        // epilogue: exp + Z/S accumulation
#pragma unroll
        for (int m = 0; m < 2; m++)
#pragma unroll
            for (int nf = 0; nf < 4; nf++) {
                int colb = ntb + wn * 32 + nf * 8 + (lane & 3) * 2;
                float2 bb = *(const float2*)(bvec + colb);
                float2 cq = *(const float2*)(&g_csq[colb]);
#pragma unroll
                for (int h = 0; h < 2; h++) {
#pragma unroll
                    for (int q = 0; q < 2; q++) {
                        float e = __expf(cL[m][nf][h * 2 + q] + (q ? bb.y : bb.x));
                        float dd = (q ? cq.y : cq.x) - 2.f * cC[m][nf][h * 2 + q];
                        zr[m * 2 + h] += e;
                        sr[m * 2 + h] = fmaf(e, dd, sr[m * 2 + h]);
                    }
                }
            }
    }

    // quad reduce (deterministic), then cross-warp via SMEM
#pragma unroll
    for (int i = 0; i < 4; i++) {
        zr[i] += __shfl_xor_sync(0xffffffffu, zr[i], 1);
        zr[i] += __shfl_xor_sync(0xffffffffu, zr[i], 2);
        sr[i] += __shfl_xor_sync(0xffffffffu, sr[i], 1);
        sr[i] += __shfl_xor_sync(0xffffffffu, sr[i], 2);
    }
    if ((lane & 3) == 0) {
#pragma unroll
        for (int m = 0; m < 2; m++)
#pragma unroll
            for (int h = 0; h < 2; h++) {
                int rloc = wm * 32 + m * 16 + h * 8 + (lane >> 2);
                redz[wn * 128 + rloc] = zr[m * 2 + h];
                reds[wn * 128 + rloc] = sr[m * 2 + h];
            }
    }
    __syncthreads();
    if (tid < MROWS) {
        float Z = 0.f, S = 0.f;
#pragma unroll
        for (int w = 0; w < 4; w++) {
            Z += redz[w * 128 + tid];
            S += reds[w * 128 + tid];
        }
        int slot = rt * MROWS + tid;
        g_Zpart[slot * SEGS + seg] = Z;
        g_Spart[slot * SEGS + seg] = S;
    }
}

// ---------------------------------------------------------------------------
__global__ void finalize_kernel(float* __restrict__ out, int D) {
    __shared__ float sred[1024];
    int tid = threadIdx.x;
    int cnt = g_cnt;
    float local = 0.f;
    for (int slot = tid; slot < cnt; slot += blockDim.x) {
        float Z = 0.f, S = 0.f;
#pragma unroll
        for (int s = 0; s < SEGS; s++) {
            Z += g_Zpart[slot * SEGS + s];
            S += g_Spart[slot * SEGS + s];
        }
        int n = g_rowidx[slot];
        local += g_tsq[n] + S / Z;
    }
    sred[tid] = local;
    __syncthreads();
    for (int o = 512; o; o >>= 1) {
        if (tid < o) sred[tid] += sred[tid + o];
        __syncthreads();
    }
    if (tid == 0) out[0] = sred[0] * (0.1f / (float)D);
}

// ---------------------------------------------------------------------------
extern "C" void kernel_launch(void* const* d_in, const int* in_sizes, int n_in,
                              void* d_out, int out_size) {
    const float* X    = (const float*)d_in[0];
    const int*   tt32 = (const int*)  d_in[1];
    const float* Tg   = (const float*)d_in[2];
    const float* W    = (const float*)d_in[3];
    const float* bp   = (const float*)d_in[4];
    const float* Cb   = (const float*)d_in[5];
    float* out = (float*)d_out;

    int N = in_sizes[1];
    int H = in_sizes[0] / N;
    int K = in_sizes[4];

    float* csq_p; cudaGetSymbolAddress((void**)&csq_p, g_csq);
    float* tsq_p; cudaGetSymbolAddress((void**)&tsq_p, g_tsq);
    __nv_bfloat16 *xb_p, *tb_p, *wb_p, *cb_p;
    cudaGetSymbolAddress((void**)&xb_p, g_Xb);
    cudaGetSymbolAddress((void**)&tb_p, g_Tb);
    cudaGetSymbolAddress((void**)&wb_p, g_Wb);
    cudaGetSymbolAddress((void**)&cb_p, g_Cb);

    cudaFuncSetAttribute(mma_kernel, cudaFuncAttributeMaxDynamicSharedMemorySize,
                         SMEM_TOTAL);

    compact_kernel<<<1, 1024>>>(tt32, N);
    rowsq_kernel<<<256, 256>>>(Cb, csq_p, K, H);
    rowsq_kernel<<<64, 256>>>(Tg, tsq_p, N, H);

    cvt_bf16_kernel<<<512, 256>>>(X, xb_p, N * H);
    cvt_bf16_kernel<<<512, 256>>>(Tg, tb_p, N * H);
    cvt_bf16_kernel<<<1024, 256>>>(W, wb_p, K * H);
    cvt_bf16_kernel<<<1024, 256>>>(Cb, cb_p, K * H);

    dim3 grid(N / MROWS, K / NSEG);
    mma_kernel<<<grid, 512, SMEM_TOTAL>>>(bp, H, K);

    finalize_kernel<<<1, 1024>>>(out, H);
}